// round 3
// baseline (speedup 1.0000x reference)
#include <cuda_runtime.h>

// Dynamic grouped conv, algebraically reduced:
//   out[b,o,h,w] = sum_{kh,kw} ker[b,o,kh,kw] * S[b,g,h+kh,w+kw]
//   S[b,g] = sum of the 8 input channels of group g (reflection-padded)
//
// R3: full 128-bit vectorization. float4 LDG in the group-sum phase,
// float4 STG in the stencil phase (4 px/thread), LDS.128 taps.
// Channel split x4 (2 ch/thread) to keep regs < 64.

static constexpr int HH = 256;
static constexpr int WW = 256;
static constexpr int IN_CH = 64;
static constexpr int OUT_CH = 64;
static constexpr int FPG = 8;
static constexpr int TH = 64;
static constexpr int TW = 64;
static constexpr int SSTR = 72;          // smem row stride (16B-aligned: 72*4=288)
// smem layout: padded col -1 -> index 3, interior col c -> index c+4 (16B aligned),
// right halo col 64 -> index 68. Rows: padded row r = global ty0 + r - 1, r in 0..65.

__device__ __forceinline__ int refl(int i, int n) {
    i = (i < 0) ? -i : i;
    return (i >= n) ? (2 * n - 2 - i) : i;
}

__global__ __launch_bounds__(256, 4)
void dynconv_fused(const float* __restrict__ x,
                   const float* __restrict__ rep,
                   const float* __restrict__ Wm,
                   float* __restrict__ out) {
    __shared__ float S[(TH + 2) * SSTR];
    __shared__ float wk[FPG * 9];

    const int bz = blockIdx.z;             // b*8 + g
    const int b  = bz >> 3;
    const int g  = bz & 7;
    const int ty0 = blockIdx.y * TH;
    const int tx0 = blockIdx.x * TW;
    const int tid = threadIdx.x;

    // ---- threads 0..71: this block's 72 dynamic weights ----
    if (tid < FPG * 9) {
        const int j = (g * FPG) * 9 + tid;          // row of W (576 x 32)
        const float* r = rep + b * 32;
        const float* w = Wm + j * 32;
        float acc = 0.f;
        #pragma unroll
        for (int i = 0; i < 32; i++) acc = fmaf(r[i], w[i], acc);
        wk[tid] = (acc > 0.f) ? acc : 0.1f * acc;
    }

    const float* xb = x + (size_t)(b * IN_CH + g * FPG) * (HH * WW);

    // ---- interior group-sum: 66 rows x 16 float4, all aligned ----
    for (int pos = tid; pos < 66 * 16; pos += 256) {
        const int r  = pos >> 4;
        const int c4 = pos & 15;
        const int gy = refl(ty0 + r - 1, HH);
        const float4* p = (const float4*)(xb + (size_t)gy * WW + tx0) + c4;
        float4 a = make_float4(0.f, 0.f, 0.f, 0.f);
        #pragma unroll
        for (int f = 0; f < FPG; f++) {
            float4 v = p[f * (HH * WW / 4)];
            a.x += v.x; a.y += v.y; a.z += v.z; a.w += v.w;
        }
        *(float4*)&S[r * SSTR + 4 + 4 * c4] = a;
    }

    // ---- halo columns (global cols tx0-1 and tx0+64), scalar ----
    for (int pos = tid; pos < 66 * 2; pos += 256) {
        const int r    = pos >> 1;
        const int side = pos & 1;
        const int gy = refl(ty0 + r - 1, HH);
        const int gx = side ? refl(tx0 + 64, WW) : refl(tx0 - 1, WW);
        const float* p = xb + (size_t)gy * WW + gx;
        float a = 0.f;
        #pragma unroll
        for (int f = 0; f < FPG; f++) a += p[f * (HH * WW)];
        S[r * SSTR + (side ? 68 : 3)] = a;
    }
    __syncthreads();

    // ---- mapping: tid = col4(4b) | chq(2b) | rowq(2b) ----
    const int col4 = tid & 15;             // 16 float4 columns
    const int grp  = tid >> 4;
    const int chq  = grp & 3;              // channel pair 2*chq, 2*chq+1
    const int rowq = grp >> 2;             // 16 rows each
    const int py0  = rowq * 16;
    const int c0   = 4 * col4;             // local col of first output pixel

    float wreg[2][9];
    #pragma unroll
    for (int o = 0; o < 2; o++)
        #pragma unroll
        for (int k = 0; k < 9; k++)
            wreg[o][k] = wk[(chq * 2 + o) * 9 + k];

    float* ob = out + ((size_t)(b * OUT_CH + g * FPG + chq * 2) * HH + ty0) * WW
                    + tx0 + c0;

    for (int j = 0; j < 16; j++) {
        const int py = py0 + j;
        // taps: 3 rows x 6 values (smem cols c0+3 .. c0+8)
        float v[3][6];
        #pragma unroll
        for (int kh = 0; kh < 3; kh++) {
            const float* row = &S[(py + kh) * SSTR + c0 + 3];
            v[kh][0] = row[0];
            float4 q = *(const float4*)(row + 1);
            v[kh][1] = q.x; v[kh][2] = q.y; v[kh][3] = q.z; v[kh][4] = q.w;
            v[kh][5] = row[5];
        }

        #pragma unroll
        for (int o = 0; o < 2; o++) {
            float4 acc;
            float* ap = (float*)&acc;
            #pragma unroll
            for (int i = 0; i < 4; i++) {
                float a = 0.f;
                #pragma unroll
                for (int kh = 0; kh < 3; kh++)
                    #pragma unroll
                    for (int kw = 0; kw < 3; kw++)
                        a = fmaf(wreg[o][kh * 3 + kw], v[kh][i + kw], a);
                ap[i] = a;
            }
            *(float4*)(ob + (size_t)o * (HH * WW) + py * WW) = acc;
        }
    }
}

extern "C" void kernel_launch(void* const* d_in, const int* in_sizes, int n_in,
                              void* d_out, int out_size) {
    const float* x   = (const float*)d_in[0];
    const float* rep = (const float*)d_in[1];
    const float* Wm  = (const float*)d_in[2];
    float* out = (float*)d_out;

    dim3 grid(WW / TW, HH / TH, 8 * 8);    // 4 x 4 x 64 = 1024 blocks
    dynconv_fused<<<grid, 256>>>(x, rep, Wm, out);
}

// round 4
// speedup vs baseline: 1.2982x; 1.2982x over previous
#include <cuda_runtime.h>

// Dynamic grouped conv, algebraically reduced:
//   out[b,o,h,w] = sum_{kh,kw} ker[b,o,kh,kw] * S[b,g,h+kh,w+kw]
//   S[b,g] = sum of the 8 input channels of group g (reflection-padded)
//
// R4: float4 LDG load phase + STG.128 stores (from R3), but stencil taps now
// use a rolling 3-row register window: only the NEW bottom row (6 floats) is
// fetched from SMEM per output row -> 3x less LDS traffic than R3.

static constexpr int HH = 256;
static constexpr int WW = 256;
static constexpr int IN_CH = 64;
static constexpr int OUT_CH = 64;
static constexpr int FPG = 8;
static constexpr int TH = 64;
static constexpr int TW = 64;
static constexpr int SSTR = 72;   // smem row stride in floats (72*4 = 288 B)
// smem col layout: halo(-1) -> 3, interior c -> c+4 (16B aligned), halo(64) -> 68

__device__ __forceinline__ int refl(int i, int n) {
    i = (i < 0) ? -i : i;
    return (i >= n) ? (2 * n - 2 - i) : i;
}

__global__ __launch_bounds__(256, 4)
void dynconv_fused(const float* __restrict__ x,
                   const float* __restrict__ rep,
                   const float* __restrict__ Wm,
                   float* __restrict__ out) {
    __shared__ float S[(TH + 2) * SSTR];
    __shared__ float wk[FPG * 9];

    const int bz = blockIdx.z;             // b*8 + g
    const int b  = bz >> 3;
    const int g  = bz & 7;
    const int ty0 = blockIdx.y * TH;
    const int tx0 = blockIdx.x * TW;
    const int tid = threadIdx.x;

    // ---- threads 0..71: this block's 72 dynamic weights ----
    if (tid < FPG * 9) {
        const int j = (g * FPG) * 9 + tid;          // row of W (576 x 32)
        const float* r = rep + b * 32;
        const float* w = Wm + j * 32;
        float acc = 0.f;
        #pragma unroll
        for (int i = 0; i < 32; i++) acc = fmaf(r[i], w[i], acc);
        wk[tid] = (acc > 0.f) ? acc : 0.1f * acc;
    }

    const float* xb = x + (size_t)(b * IN_CH + g * FPG) * (HH * WW);

    // ---- interior group-sum: 66 rows x 16 float4, all aligned ----
    for (int pos = tid; pos < 66 * 16; pos += 256) {
        const int r  = pos >> 4;
        const int c4 = pos & 15;
        const int gy = refl(ty0 + r - 1, HH);
        const float4* p = (const float4*)(xb + (size_t)gy * WW + tx0) + c4;
        float4 a = make_float4(0.f, 0.f, 0.f, 0.f);
        #pragma unroll
        for (int f = 0; f < FPG; f++) {
            float4 v = p[f * (HH * WW / 4)];
            a.x += v.x; a.y += v.y; a.z += v.z; a.w += v.w;
        }
        *(float4*)&S[r * SSTR + 4 + 4 * c4] = a;
    }

    // ---- halo columns (global cols tx0-1 and tx0+64), scalar ----
    for (int pos = tid; pos < 66 * 2; pos += 256) {
        const int r    = pos >> 1;
        const int side = pos & 1;
        const int gy = refl(ty0 + r - 1, HH);
        const int gx = side ? refl(tx0 + 64, WW) : refl(tx0 - 1, WW);
        const float* p = xb + (size_t)gy * WW + gx;
        float a = 0.f;
        #pragma unroll
        for (int f = 0; f < FPG; f++) a += p[f * (HH * WW)];
        S[r * SSTR + (side ? 68 : 3)] = a;
    }
    __syncthreads();

    // ---- mapping: tid = col4(4b) | chq(2b) | rowq(2b) ----
    const int col4 = tid & 15;             // 16 float4 columns
    const int grp  = tid >> 4;
    const int chq  = grp & 3;              // channel pair 2*chq, 2*chq+1
    const int rowq = grp >> 2;             // 4 strips of 16 rows
    const int py0  = rowq * 16;
    const int c0   = 4 * col4;

    float wreg[2][9];
    #pragma unroll
    for (int o = 0; o < 2; o++)
        #pragma unroll
        for (int k = 0; k < 9; k++)
            wreg[o][k] = wk[(chq * 2 + o) * 9 + k];

    float* ob = out + ((size_t)(b * OUT_CH + g * FPG + chq * 2) * HH + ty0) * WW
                    + tx0 + c0;

    // rolling 3-row tap window in registers
    float v[3][6];
    {
        #pragma unroll
        for (int kh = 0; kh < 2; kh++) {
            const float* row = &S[(py0 + kh) * SSTR + c0 + 3];
            v[kh][0] = row[0];
            float4 q = *(const float4*)(row + 1);
            v[kh][1] = q.x; v[kh][2] = q.y; v[kh][3] = q.z; v[kh][4] = q.w;
            v[kh][5] = row[5];
        }
    }

    #pragma unroll 4
    for (int j = 0; j < 16; j++) {
        // fetch new bottom row (padded row py0 + j + 2)
        {
            const float* row = &S[(py0 + j + 2) * SSTR + c0 + 3];
            v[2][0] = row[0];
            float4 q = *(const float4*)(row + 1);
            v[2][1] = q.x; v[2][2] = q.y; v[2][3] = q.z; v[2][4] = q.w;
            v[2][5] = row[5];
        }

        #pragma unroll
        for (int o = 0; o < 2; o++) {
            float4 acc;
            float* ap = (float*)&acc;
            #pragma unroll
            for (int i = 0; i < 4; i++) {
                float a = 0.f;
                #pragma unroll
                for (int kh = 0; kh < 3; kh++)
                    #pragma unroll
                    for (int kw = 0; kw < 3; kw++)
                        a = fmaf(wreg[o][kh * 3 + kw], v[kh][i + kw], a);
                ap[i] = a;
            }
            *(float4*)(ob + (size_t)o * (HH * WW) + (py0 + j) * WW) = acc;
        }

        // rotate window
        #pragma unroll
        for (int t = 0; t < 6; t++) { v[0][t] = v[1][t]; v[1][t] = v[2][t]; }
    }
}

extern "C" void kernel_launch(void* const* d_in, const int* in_sizes, int n_in,
                              void* d_out, int out_size) {
    const float* x   = (const float*)d_in[0];
    const float* rep = (const float*)d_in[1];
    const float* Wm  = (const float*)d_in[2];
    float* out = (float*)d_out;

    dim3 grid(WW / TW, HH / TH, 8 * 8);    // 4 x 4 x 64 = 1024 blocks
    dynconv_fused<<<grid, 256>>>(x, rep, Wm, out);
}

// round 5
// speedup vs baseline: 1.2989x; 1.0006x over previous
#include <cuda_runtime.h>

// Dynamic grouped conv, algebraically reduced:
//   out[b,o,h,w] = sum_{kh,kw} ker[b,o,kh,kw] * S[b,g,h+kh,w+kw]
//   S[b,g] = sum of the 8 input channels of group g (reflection-padded)
//
// R5: occupancy push. 512-thread CTAs, 1 output channel per thread
// (9 weight regs), rolling 3-row register tap window, float4 LDG/STG.
// __launch_bounds__(512,3) -> 48 warps/SM target.

static constexpr int HH = 256;
static constexpr int WW = 256;
static constexpr int IN_CH = 64;
static constexpr int OUT_CH = 64;
static constexpr int FPG = 8;
static constexpr int TH = 64;
static constexpr int TW = 64;
static constexpr int SSTR = 72;   // smem row stride in floats (72*4 = 288 B)
// smem col layout: halo(-1) -> 3, interior c -> c+4 (16B aligned), halo(64) -> 68

__device__ __forceinline__ int refl(int i, int n) {
    i = (i < 0) ? -i : i;
    return (i >= n) ? (2 * n - 2 - i) : i;
}

__global__ __launch_bounds__(512, 3)
void dynconv_fused(const float* __restrict__ x,
                   const float* __restrict__ rep,
                   const float* __restrict__ Wm,
                   float* __restrict__ out) {
    __shared__ float S[(TH + 2) * SSTR];
    __shared__ float wk[FPG * 9];

    const int bz = blockIdx.z;             // b*8 + g
    const int b  = bz >> 3;
    const int g  = bz & 7;
    const int ty0 = blockIdx.y * TH;
    const int tx0 = blockIdx.x * TW;
    const int tid = threadIdx.x;

    // ---- threads 0..71: this block's 72 dynamic weights ----
    if (tid < FPG * 9) {
        const int j = (g * FPG) * 9 + tid;          // row of W (576 x 32)
        const float* r = rep + b * 32;
        const float* w = Wm + j * 32;
        float acc = 0.f;
        #pragma unroll
        for (int i = 0; i < 32; i++) acc = fmaf(r[i], w[i], acc);
        wk[tid] = (acc > 0.f) ? acc : 0.1f * acc;
    }

    const float* xb = x + (size_t)(b * IN_CH + g * FPG) * (HH * WW);

    // ---- interior group-sum: 66 rows x 16 float4, all aligned ----
    for (int pos = tid; pos < 66 * 16; pos += 512) {
        const int r  = pos >> 4;
        const int c4 = pos & 15;
        const int gy = refl(ty0 + r - 1, HH);
        const float4* p = (const float4*)(xb + (size_t)gy * WW + tx0) + c4;
        float4 a = make_float4(0.f, 0.f, 0.f, 0.f);
        #pragma unroll
        for (int f = 0; f < FPG; f++) {
            float4 v = p[f * (HH * WW / 4)];
            a.x += v.x; a.y += v.y; a.z += v.z; a.w += v.w;
        }
        *(float4*)&S[r * SSTR + 4 + 4 * c4] = a;
    }

    // ---- halo columns (global cols tx0-1 and tx0+64), scalar ----
    for (int pos = tid; pos < 66 * 2; pos += 512) {
        const int r    = pos >> 1;
        const int side = pos & 1;
        const int gy = refl(ty0 + r - 1, HH);
        const int gx = side ? refl(tx0 + 64, WW) : refl(tx0 - 1, WW);
        const float* p = xb + (size_t)gy * WW + gx;
        float a = 0.f;
        #pragma unroll
        for (int f = 0; f < FPG; f++) a += p[f * (HH * WW)];
        S[r * SSTR + (side ? 68 : 3)] = a;
    }
    __syncthreads();

    // ---- mapping: tid = col4(4b) | ch(3b) | rowq(2b) ----
    const int col4 = tid & 15;             // 16 float4 columns
    const int ch   = (tid >> 4) & 7;       // 1 output channel per thread
    const int rowq = tid >> 7;             // 4 strips of 16 rows
    const int py0  = rowq * 16;
    const int c0   = 4 * col4;

    float wreg[9];
    #pragma unroll
    for (int k = 0; k < 9; k++) wreg[k] = wk[ch * 9 + k];

    float* ob = out + ((size_t)(b * OUT_CH + g * FPG + ch) * HH + ty0) * WW
                    + tx0 + c0;

    // rolling 3-row tap window in registers
    float v[3][6];
    #pragma unroll
    for (int kh = 0; kh < 2; kh++) {
        const float* row = &S[(py0 + kh) * SSTR + c0 + 3];
        v[kh][0] = row[0];
        float4 q = *(const float4*)(row + 1);
        v[kh][1] = q.x; v[kh][2] = q.y; v[kh][3] = q.z; v[kh][4] = q.w;
        v[kh][5] = row[5];
    }

    #pragma unroll 4
    for (int j = 0; j < 16; j++) {
        // fetch new bottom row (padded row py0 + j + 2)
        {
            const float* row = &S[(py0 + j + 2) * SSTR + c0 + 3];
            v[2][0] = row[0];
            float4 q = *(const float4*)(row + 1);
            v[2][1] = q.x; v[2][2] = q.y; v[2][3] = q.z; v[2][4] = q.w;
            v[2][5] = row[5];
        }

        float4 acc;
        float* ap = (float*)&acc;
        #pragma unroll
        for (int i = 0; i < 4; i++) {
            float a = 0.f;
            #pragma unroll
            for (int kh = 0; kh < 3; kh++)
                #pragma unroll
                for (int kw = 0; kw < 3; kw++)
                    a = fmaf(wreg[kh * 3 + kw], v[kh][i + kw], a);
            ap[i] = a;
        }
        *(float4*)(ob + (size_t)(py0 + j) * WW) = acc;

        // rotate window
        #pragma unroll
        for (int t = 0; t < 6; t++) { v[0][t] = v[1][t]; v[1][t] = v[2][t]; }
    }
}

extern "C" void kernel_launch(void* const* d_in, const int* in_sizes, int n_in,
                              void* d_out, int out_size) {
    const float* x   = (const float*)d_in[0];
    const float* rep = (const float*)d_in[1];
    const float* Wm  = (const float*)d_in[2];
    float* out = (float*)d_out;

    dim3 grid(WW / TW, HH / TH, 8 * 8);    // 4 x 4 x 64 = 1024 blocks
    dynconv_fused<<<grid, 512>>>(x, rep, Wm, out);
}